// round 3
// baseline (speedup 1.0000x reference)
#include <cuda_runtime.h>
#include <math.h>
#include <stdint.h>

// ---------------------------------------------------------------------------
// LSTM + differentiable stack, 259 sequential steps, persistent kernel.
// 128 CTAs, 2 grid barriers per step.
//  Phase A: CTA n computes 16 gate columns (4 hidden units x 4 gates) for all
//           128 batch rows, full K (704 or 512), weights resident in SMEM as
//           duplicated f32x2, activations streamed [k][b] via cp.async double
//           buffer, FFMA2 inner loop. Epilogue: LSTM cell for its 4 units
//           (c-state persistent in SMEM), h written transposed+double-buffered.
//  Phase B: CTA b computes o194 = h[b] @ Wr^T + br, then the stack update
//           (suffix scan, A, r_t -> transposed), and log-softmax out (t>=129).
// ---------------------------------------------------------------------------

#define BATCH   128
#define HID     512
#define INPD    128
#define STKD    64
#define MAXT    259
#define NSTEPS  259
#define KSTART  129
#define OCOLS   194

#define GRIDN   128
#define NTHR    256
#define NCHUNK  44          // 704 / 16
#define KC      16

// smem layout (floats)
#define OFF_WD  0           // 11264 u64  = 22528 floats (W dup f32x2, [k][16])
#define OFF_AS  22528       // 2 x 16x128 A-tile double buffer
#define OFF_GS  26624       // 16 x 132 gate exchange
#define OFF_SC  28736       // 512 c-state
#define OFF_SB  29248       // 16 bias
#define SMEMF   29264
#define SMEMB   (SMEMF * 4) // 117056 bytes

__device__ float d_xT[129 * 128 * 128];          // x transposed [t][k][b]
__device__ float d_RH[(64 + 1024) * 128];        // rows: 0..63 r ; 64..575 h0 ; 576..1087 h1
__device__ float d_s[BATCH * MAXT];
__device__ float d_V[BATCH * MAXT * STKD];
__device__ unsigned g_bar;

__device__ __forceinline__ float sigf(float x) { return 1.0f / (1.0f + expf(-x)); }

#define FFMA2(acc, a, w) \
    asm volatile("fma.rn.f32x2 %0, %1, %2, %0;" : "+l"(acc) : "l"(a), "l"(w))

__device__ __forceinline__ void grid_sync(unsigned &n) {
    __syncthreads();
    n += (unsigned)GRIDN;
    if (threadIdx.x == 0) {
        __threadfence();
        atomicAdd(&g_bar, 1u);
        while (*((volatile unsigned *)&g_bar) < n) { }
        __threadfence();
    }
    __syncthreads();
}

__device__ __forceinline__ void load_chunk(int c, int t, int hrd,
                                           const float *__restrict__ x_unused,
                                           float *As, int tid) {
    const float *src;
    if (c < 8)       src = d_xT + ((size_t)t * 128 + c * 16) * 128;
    else if (c < 12) src = d_RH + (size_t)((c - 8) * 16) * 128;
    else             src = d_RH + (size_t)(64 + hrd * 512 + (c - 12) * 16) * 128;
    float *dst = As + (c & 1) * (KC * 128);
#pragma unroll
    for (int q = 0; q < 2; ++q) {
        int seg = tid + q * NTHR;          // 0..511 segments of 16B
        unsigned sdst = (unsigned)__cvta_generic_to_shared(dst + seg * 4);
        const float *g = src + seg * 4;
        asm volatile("cp.async.ca.shared.global [%0], [%1], 16;" :: "r"(sdst), "l"(g));
    }
    asm volatile("cp.async.commit_group;" ::: "memory");
}

__global__ void __launch_bounds__(NTHR, 1)
lstm_stack_kernel(const float *__restrict__ x,
                  const float *__restrict__ Wih, const float *__restrict__ bih,
                  const float *__restrict__ Whh, const float *__restrict__ bhh,
                  const float *__restrict__ Wr, const float *__restrict__ br,
                  float *__restrict__ out) {
    extern __shared__ __align__(16) float smf[];
    unsigned long long *Wd = (unsigned long long *)(smf + OFF_WD);
    float *As = smf + OFF_AS;
    float *gs = smf + OFF_GS;
    float *sc = smf + OFF_SC;
    float *sb = smf + OFF_SB;
    // phase-B scratch aliases the A-tile region (safe: separated by barriers)
    float *pb   = smf + OFF_AS;
    float *so   = pb;            // 208
    float *ss   = pb + 208;      // 288
    float *ssuf = pb + 496;      // 288
    float *sA   = pb + 784;      // 288
    float *csum = pb + 1072;     // 16
    float *sred = pb + 1088;     // 256
    float *hsm  = pb + 1344;     // 512

    const int tid  = threadIdx.x;
    const int bidx = blockIdx.x;
    const int lane = tid & 31, wid = tid >> 5;
    unsigned n = 0;

    // ---------------- prologue: transpose x[t] -> d_xT[t][k][b] -------------
    {
        float *tile = smf;  // 128 x 132 scratch (overlaps Wd; loaded later)
        for (int p = bidx; p < KSTART; p += GRIDN) {
#pragma unroll
            for (int q = 0; q < 16; ++q) {
                int idx = q * 1024 + tid * 4;
                int b = idx >> 7, k = idx & 127;
                float4 v = *(const float4 *)(x + ((size_t)p * 128 + b) * 128 + k);
                tile[b * 132 + k]     = v.x;
                tile[b * 132 + k + 1] = v.y;
                tile[b * 132 + k + 2] = v.z;
                tile[b * 132 + k + 3] = v.w;
            }
            __syncthreads();
#pragma unroll
            for (int q = 0; q < 16; ++q) {
                int idx = q * 1024 + tid * 4;
                int k = idx >> 7, b = idx & 127;
                float4 v = make_float4(tile[b * 132 + k], tile[(b + 1) * 132 + k],
                                       tile[(b + 2) * 132 + k], tile[(b + 3) * 132 + k]);
                *(float4 *)(d_xT + ((size_t)p * 128 + k) * 128 + b) = v;
            }
            __syncthreads();
        }
    }
    grid_sync(n);

    // ---------------- persistent loads: W (dup f32x2), bias, c-state --------
    for (int idx = tid; idx < 704 * 16; idx += NTHR) {
        int k = idx >> 4, cidx = idx & 15;
        int m = cidx >> 2, u = cidx & 3;
        int grow = m * 512 + bidx * 4 + u;
        float w = (k < 192) ? Wih[(size_t)grow * 192 + k]
                            : Whh[(size_t)grow * 512 + (k - 192)];
        unsigned ub = __float_as_uint(w);
        Wd[idx] = (unsigned long long)ub | ((unsigned long long)ub << 32);
    }
    if (tid < 16) {
        int m = tid >> 2, u = tid & 3;
        int grow = m * 512 + bidx * 4 + u;
        sb[tid] = bih[grow] + bhh[grow];
    }
    for (int idx = tid; idx < 512; idx += NTHR) sc[idx] = 0.0f;
    __syncthreads();

    const int tx = tid & 15;       // column within 16
    const int ty = tid >> 4;       // batch octet 0..15

    // =========================== main time loop =============================
    for (int t = 0; t < NSTEPS; ++t) {
        const int hrd = t & 1, hwr = (t + 1) & 1;
        const int cbeg = (t < KSTART) ? 0 : 8;

        // ---------------- Phase A: gate GEMM + cell ----------------
        unsigned long long acc0 = 0ull, acc1 = 0ull, acc2 = 0ull, acc3 = 0ull;
        load_chunk(cbeg, t, hrd, x, As, tid);
        for (int c = cbeg; c < NCHUNK; ++c) {
            if (c + 1 < NCHUNK) {
                load_chunk(c + 1, t, hrd, x, As, tid);
                asm volatile("cp.async.wait_group 1;" ::: "memory");
            } else {
                asm volatile("cp.async.wait_group 0;" ::: "memory");
            }
            __syncthreads();
            const float *Asb = As + (c & 1) * (KC * 128);
            const int kg0 = c * 16;
#pragma unroll
            for (int kk = 0; kk < KC; ++kk) {
                const ulonglong2 *ap =
                    (const ulonglong2 *)(Asb + kk * 128 + ty * 8);
                ulonglong2 a01 = ap[0];
                ulonglong2 a23 = ap[1];
                unsigned long long w = Wd[(kg0 + kk) * 16 + tx];
                FFMA2(acc0, a01.x, w);
                FFMA2(acc1, a01.y, w);
                FFMA2(acc2, a23.x, w);
                FFMA2(acc3, a23.y, w);
            }
            __syncthreads();
        }
        // epilogue: unpack + bias -> gs[col][b]
        {
            float bsum = sb[tx];
            float v0 = __uint_as_float((unsigned)acc0) + bsum;
            float v1 = __uint_as_float((unsigned)(acc0 >> 32)) + bsum;
            float v2 = __uint_as_float((unsigned)acc1) + bsum;
            float v3 = __uint_as_float((unsigned)(acc1 >> 32)) + bsum;
            float v4 = __uint_as_float((unsigned)acc2) + bsum;
            float v5 = __uint_as_float((unsigned)(acc2 >> 32)) + bsum;
            float v6 = __uint_as_float((unsigned)acc3) + bsum;
            float v7 = __uint_as_float((unsigned)(acc3 >> 32)) + bsum;
            float *gp = gs + tx * 132 + ty * 8;
            *(float4 *)gp       = make_float4(v0, v1, v2, v3);
            *(float4 *)(gp + 4) = make_float4(v4, v5, v6, v7);
        }
        __syncthreads();
        // cell update for this CTA's 4 hidden units, all 128 batches
#pragma unroll
        for (int r = 0; r < 2; ++r) {
            int idx = tid + r * NTHR;        // 0..511
            int u = idx >> 7, b = idx & 127;
            float gi = gs[u * 132 + b];
            float gf = gs[(4 + u) * 132 + b];
            float gg = gs[(8 + u) * 132 + b];
            float go = gs[(12 + u) * 132 + b];
            float ig = sigf(gi), fg = sigf(gf);
            float tg = tanhf(gg), og = sigf(go);
            float c2 = fg * sc[idx] + ig * tg;
            sc[idx] = c2;
            d_RH[(size_t)(64 + hwr * 512 + bidx * 4 + u) * 128 + b] = og * tanhf(c2);
        }
        grid_sync(n);

        // ---------------- Phase B: readout + stack (CTA = batch row) -------
        const int b = bidx;
        for (int j = tid; j < HID; j += NTHR)
            hsm[j] = d_RH[(size_t)(64 + hwr * 512 + j) * 128 + b];
        __syncthreads();
        if (tid < OCOLS) {
            float a0 = 0.f, a1 = 0.f, a2 = 0.f, a3 = 0.f;
            const float4 *wr4 = (const float4 *)(Wr + (size_t)tid * HID);
            const float4 *h4  = (const float4 *)hsm;
#pragma unroll 4
            for (int k4 = 0; k4 < HID / 4; ++k4) {
                float4 w = wr4[k4], h = h4[k4];
                a0 = fmaf(h.x, w.x, a0);
                a1 = fmaf(h.y, w.y, a1);
                a2 = fmaf(h.z, w.z, a2);
                a3 = fmaf(h.w, w.w, a3);
            }
            so[tid] = (a0 + a1) + (a2 + a3) + br[tid];
        }
        for (int i = tid; i < 288; i += NTHR)
            ss[i] = (i < MAXT) ? d_s[b * MAXT + i] : 0.0f;
        __syncthreads();

        if (tid < STKD) d_V[((size_t)b * MAXT + t) * STKD + tid] = so[tid];
        float u_ = sigf(so[192]);
        float dd = sigf(so[193]);

        // per-32-chunk inclusive suffix scans
        for (int cch = wid; cch < 9; cch += 8) {
            float v = ss[cch * 32 + lane];
#pragma unroll
            for (int o = 1; o < 32; o <<= 1) {
                float tv = __shfl_down_sync(0xffffffffu, v, o);
                if (lane + o < 32) v += tv;
            }
            ssuf[cch * 32 + lane] = v;
            if (lane == 0) csum[cch] = v;
        }
        __syncthreads();
        if (wid == 0) {
            float tv = (lane < 9) ? csum[lane] : 0.0f;
            float vv = tv;
#pragma unroll
            for (int o = 1; o < 16; o <<= 1) {
                float sh = __shfl_down_sync(0xffffffffu, vv, o);
                if (lane + o < 16) vv += sh;
            }
            if (lane < 9) csum[lane] = vv - tv;   // strict suffix of chunk totals
        }
        __syncthreads();

        for (int i = tid; i < MAXT; i += NTHR) {
            float si   = ss[i];
            float prod = ssuf[i] + csum[i >> 5] - si;     // sum_{j>i} s[j]
            float sp   = fmaxf(0.0f, si - fmaxf(0.0f, u_ - prod));
            if (i == t) sp = dd;
            float inner = fmaxf(0.0f, 1.0f - prod - sp);
            sA[i] = fminf(sp, inner);
            if (i <= t) d_s[b * MAXT + i] = sp;
        }
        __syncthreads();

        // r_t[d] = sum_{i<=t} A[i] * V[b][i][d]  -> stored transposed
        {
            const int dcol = tid & 63, q = tid >> 6;
            float acc = 0.0f;
            for (int i = q; i <= t; i += 4)
                acc += sA[i] * d_V[((size_t)b * MAXT + i) * STKD + dcol];
            sred[q * 64 + dcol] = acc;
        }
        __syncthreads();
        if (tid < STKD)
            d_RH[(size_t)tid * 128 + b] =
                sred[tid] + sred[64 + tid] + sred[128 + tid] + sred[192 + tid];

        if (t >= KSTART) {
            __syncthreads();
            float v = (tid < INPD) ? so[STKD + tid] : -1e30f;
            float m = v;
#pragma unroll
            for (int o = 16; o; o >>= 1) m = fmaxf(m, __shfl_xor_sync(0xffffffffu, m, o));
            if (lane == 0) csum[wid] = m;
            __syncthreads();
            float mm = csum[0];
#pragma unroll
            for (int w = 1; w < 8; ++w) mm = fmaxf(mm, csum[w]);
            float e = (tid < INPD) ? expf(v - mm) : 0.0f;
#pragma unroll
            for (int o = 16; o; o >>= 1) e += __shfl_xor_sync(0xffffffffu, e, o);
            if (lane == 0) csum[8 + wid] = e;
            __syncthreads();
            float tot = 0.0f;
#pragma unroll
            for (int w = 0; w < 8; ++w) tot += csum[8 + w];
            float ls = logf(tot);
            if (tid < INPD)
                out[(((size_t)(t - KSTART)) * BATCH + b) * INPD + tid] = v - mm - ls;
        }
        grid_sync(n);
    }
}

extern "C" void kernel_launch(void *const *d_in, const int *in_sizes, int n_in,
                              void *d_out, int out_size) {
    (void)in_sizes; (void)n_in; (void)out_size;
    const float *x   = (const float *)d_in[0];
    const float *Wih = (const float *)d_in[1];
    const float *bih = (const float *)d_in[2];
    const float *Whh = (const float *)d_in[3];
    const float *bhh = (const float *)d_in[4];
    const float *Wr  = (const float *)d_in[5];
    const float *br  = (const float *)d_in[6];
    float *out = (float *)d_out;

    cudaFuncSetAttribute(lstm_stack_kernel,
                         cudaFuncAttributeMaxDynamicSharedMemorySize, SMEMB);

    void *p;
    cudaGetSymbolAddress(&p, d_RH);  cudaMemsetAsync(p, 0, sizeof(float) * (64 + 1024) * 128);
    cudaGetSymbolAddress(&p, d_s);   cudaMemsetAsync(p, 0, sizeof(float) * BATCH * MAXT);
    cudaGetSymbolAddress(&p, g_bar); cudaMemsetAsync(p, 0, sizeof(unsigned));

    lstm_stack_kernel<<<GRIDN, NTHR, SMEMB>>>(x, Wih, bih, Whh, bhh, Wr, br, out);
}

// round 4
// speedup vs baseline: 1.0033x; 1.0033x over previous
#include <cuda_runtime.h>
#include <math.h>
#include <stdint.h>

// ---------------------------------------------------------------------------
// LSTM + differentiable stack, 259 sequential steps, persistent kernel.
// 128 CTAs, 2 grid barriers per step.
//  Phase A: CTA n computes 16 gate columns (4 hidden units x 4 gates) for all
//           128 batch rows, full K (704 or 512), weights resident in SMEM as
//           duplicated f32x2, activations streamed [k][b] via cp.async double
//           buffer, FFMA2 inner loop. Epilogue: LSTM cell for its 4 units
//           (c-state persistent in SMEM), h written transposed+double-buffered.
//  Phase B: CTA b computes o194 = h[b] @ Wr^T + br, then the stack update
//           (suffix scan, A, r_t -> transposed), and log-softmax out (t>=129).
// ---------------------------------------------------------------------------

#define BATCH   128
#define HID     512
#define INPD    128
#define STKD    64
#define MAXT    259
#define NSTEPS  259
#define KSTART  129
#define OCOLS   194

#define GRIDN   128
#define NTHR    256
#define NCHUNK  44          // 704 / 16
#define KC      16

// smem layout (floats)
#define OFF_WD  0           // 11264 u64  = 22528 floats (W dup f32x2, [k][16])
#define OFF_AS  22528       // 2 x 16x128 A-tile double buffer
#define OFF_GS  26624       // 16 x 132 gate exchange
#define OFF_SC  28736       // 512 c-state
#define OFF_SB  29248       // 16 bias
#define SMEMF   29264
#define SMEMB   (SMEMF * 4) // 117056 bytes

__device__ float d_xT[129 * 128 * 128];          // x transposed [t][k][b]
__device__ float d_RH[(64 + 1024) * 128];        // rows: 0..63 r ; 64..575 h0 ; 576..1087 h1
__device__ float d_s[BATCH * MAXT];
__device__ float d_V[BATCH * MAXT * STKD];
__device__ unsigned g_bar;

__device__ __forceinline__ float sigf(float x) { return 1.0f / (1.0f + expf(-x)); }

#define FFMA2(acc, a, w) \
    asm volatile("fma.rn.f32x2 %0, %1, %2, %0;" : "+l"(acc) : "l"(a), "l"(w))

__device__ __forceinline__ void grid_sync(unsigned &n) {
    __syncthreads();
    n += (unsigned)GRIDN;
    if (threadIdx.x == 0) {
        __threadfence();
        atomicAdd(&g_bar, 1u);
        while (*((volatile unsigned *)&g_bar) < n) { }
        __threadfence();
    }
    __syncthreads();
}

__device__ __forceinline__ void load_chunk(int c, int t, int hrd,
                                           const float *__restrict__ x_unused,
                                           float *As, int tid) {
    const float *src;
    if (c < 8)       src = d_xT + ((size_t)t * 128 + c * 16) * 128;
    else if (c < 12) src = d_RH + (size_t)((c - 8) * 16) * 128;
    else             src = d_RH + (size_t)(64 + hrd * 512 + (c - 12) * 16) * 128;
    float *dst = As + (c & 1) * (KC * 128);
#pragma unroll
    for (int q = 0; q < 2; ++q) {
        int seg = tid + q * NTHR;          // 0..511 segments of 16B
        unsigned sdst = (unsigned)__cvta_generic_to_shared(dst + seg * 4);
        const float *g = src + seg * 4;
        asm volatile("cp.async.ca.shared.global [%0], [%1], 16;" :: "r"(sdst), "l"(g));
    }
    asm volatile("cp.async.commit_group;" ::: "memory");
}

__global__ void __launch_bounds__(NTHR, 1)
lstm_stack_kernel(const float *__restrict__ x,
                  const float *__restrict__ Wih, const float *__restrict__ bih,
                  const float *__restrict__ Whh, const float *__restrict__ bhh,
                  const float *__restrict__ Wr, const float *__restrict__ br,
                  float *__restrict__ out) {
    extern __shared__ __align__(16) float smf[];
    unsigned long long *Wd = (unsigned long long *)(smf + OFF_WD);
    float *As = smf + OFF_AS;
    float *gs = smf + OFF_GS;
    float *sc = smf + OFF_SC;
    float *sb = smf + OFF_SB;
    // phase-B scratch aliases the A-tile region (safe: separated by barriers)
    float *pb   = smf + OFF_AS;
    float *so   = pb;            // 208
    float *ss   = pb + 208;      // 288
    float *ssuf = pb + 496;      // 288
    float *sA   = pb + 784;      // 288
    float *csum = pb + 1072;     // 16
    float *sred = pb + 1088;     // 256
    float *hsm  = pb + 1344;     // 512

    const int tid  = threadIdx.x;
    const int bidx = blockIdx.x;
    const int lane = tid & 31, wid = tid >> 5;
    unsigned n = 0;

    // ---------------- prologue: transpose x[t] -> d_xT[t][k][b] -------------
    {
        float *tile = smf;  // 128 x 132 scratch (overlaps Wd; loaded later)
        for (int p = bidx; p < KSTART; p += GRIDN) {
#pragma unroll
            for (int q = 0; q < 16; ++q) {
                int idx = q * 1024 + tid * 4;
                int b = idx >> 7, k = idx & 127;
                float4 v = *(const float4 *)(x + ((size_t)p * 128 + b) * 128 + k);
                tile[b * 132 + k]     = v.x;
                tile[b * 132 + k + 1] = v.y;
                tile[b * 132 + k + 2] = v.z;
                tile[b * 132 + k + 3] = v.w;
            }
            __syncthreads();
#pragma unroll
            for (int q = 0; q < 16; ++q) {
                int idx = q * 1024 + tid * 4;
                int k = idx >> 7, b = idx & 127;
                float4 v = make_float4(tile[b * 132 + k], tile[(b + 1) * 132 + k],
                                       tile[(b + 2) * 132 + k], tile[(b + 3) * 132 + k]);
                *(float4 *)(d_xT + ((size_t)p * 128 + k) * 128 + b) = v;
            }
            __syncthreads();
        }
    }
    grid_sync(n);

    // ---------------- persistent loads: W (dup f32x2), bias, c-state --------
    for (int idx = tid; idx < 704 * 16; idx += NTHR) {
        int k = idx >> 4, cidx = idx & 15;
        int m = cidx >> 2, u = cidx & 3;
        int grow = m * 512 + bidx * 4 + u;
        float w = (k < 192) ? Wih[(size_t)grow * 192 + k]
                            : Whh[(size_t)grow * 512 + (k - 192)];
        unsigned ub = __float_as_uint(w);
        Wd[idx] = (unsigned long long)ub | ((unsigned long long)ub << 32);
    }
    if (tid < 16) {
        int m = tid >> 2, u = tid & 3;
        int grow = m * 512 + bidx * 4 + u;
        sb[tid] = bih[grow] + bhh[grow];
    }
    for (int idx = tid; idx < 512; idx += NTHR) sc[idx] = 0.0f;
    __syncthreads();

    const int tx = tid & 15;       // column within 16
    const int ty = tid >> 4;       // batch octet 0..15

    // =========================== main time loop =============================
    for (int t = 0; t < NSTEPS; ++t) {
        const int hrd = t & 1, hwr = (t + 1) & 1;
        const int cbeg = (t < KSTART) ? 0 : 8;

        // ---------------- Phase A: gate GEMM + cell ----------------
        unsigned long long acc0 = 0ull, acc1 = 0ull, acc2 = 0ull, acc3 = 0ull;
        load_chunk(cbeg, t, hrd, x, As, tid);
        for (int c = cbeg; c < NCHUNK; ++c) {
            if (c + 1 < NCHUNK) {
                load_chunk(c + 1, t, hrd, x, As, tid);
                asm volatile("cp.async.wait_group 1;" ::: "memory");
            } else {
                asm volatile("cp.async.wait_group 0;" ::: "memory");
            }
            __syncthreads();
            const float *Asb = As + (c & 1) * (KC * 128);
            const int kg0 = c * 16;
#pragma unroll
            for (int kk = 0; kk < KC; ++kk) {
                const ulonglong2 *ap =
                    (const ulonglong2 *)(Asb + kk * 128 + ty * 8);
                ulonglong2 a01 = ap[0];
                ulonglong2 a23 = ap[1];
                unsigned long long w = Wd[(kg0 + kk) * 16 + tx];
                FFMA2(acc0, a01.x, w);
                FFMA2(acc1, a01.y, w);
                FFMA2(acc2, a23.x, w);
                FFMA2(acc3, a23.y, w);
            }
            __syncthreads();
        }
        // epilogue: unpack + bias -> gs[col][b]
        {
            float bsum = sb[tx];
            float v0 = __uint_as_float((unsigned)acc0) + bsum;
            float v1 = __uint_as_float((unsigned)(acc0 >> 32)) + bsum;
            float v2 = __uint_as_float((unsigned)acc1) + bsum;
            float v3 = __uint_as_float((unsigned)(acc1 >> 32)) + bsum;
            float v4 = __uint_as_float((unsigned)acc2) + bsum;
            float v5 = __uint_as_float((unsigned)(acc2 >> 32)) + bsum;
            float v6 = __uint_as_float((unsigned)acc3) + bsum;
            float v7 = __uint_as_float((unsigned)(acc3 >> 32)) + bsum;
            float *gp = gs + tx * 132 + ty * 8;
            *(float4 *)gp       = make_float4(v0, v1, v2, v3);
            *(float4 *)(gp + 4) = make_float4(v4, v5, v6, v7);
        }
        __syncthreads();
        // cell update for this CTA's 4 hidden units, all 128 batches
#pragma unroll
        for (int r = 0; r < 2; ++r) {
            int idx = tid + r * NTHR;        // 0..511
            int u = idx >> 7, b = idx & 127;
            float gi = gs[u * 132 + b];
            float gf = gs[(4 + u) * 132 + b];
            float gg = gs[(8 + u) * 132 + b];
            float go = gs[(12 + u) * 132 + b];
            float ig = sigf(gi), fg = sigf(gf);
            float tg = tanhf(gg), og = sigf(go);
            float c2 = fg * sc[idx] + ig * tg;
            sc[idx] = c2;
            d_RH[(size_t)(64 + hwr * 512 + bidx * 4 + u) * 128 + b] = og * tanhf(c2);
        }
        grid_sync(n);

        // ---------------- Phase B: readout + stack (CTA = batch row) -------
        const int b = bidx;
        for (int j = tid; j < HID; j += NTHR)
            hsm[j] = d_RH[(size_t)(64 + hwr * 512 + j) * 128 + b];
        __syncthreads();
        if (tid < OCOLS) {
            float a0 = 0.f, a1 = 0.f, a2 = 0.f, a3 = 0.f;
            const float4 *wr4 = (const float4 *)(Wr + (size_t)tid * HID);
            const float4 *h4  = (const float4 *)hsm;
#pragma unroll 4
            for (int k4 = 0; k4 < HID / 4; ++k4) {
                float4 w = wr4[k4], h = h4[k4];
                a0 = fmaf(h.x, w.x, a0);
                a1 = fmaf(h.y, w.y, a1);
                a2 = fmaf(h.z, w.z, a2);
                a3 = fmaf(h.w, w.w, a3);
            }
            so[tid] = (a0 + a1) + (a2 + a3) + br[tid];
        }
        for (int i = tid; i < 288; i += NTHR)
            ss[i] = (i < MAXT) ? d_s[b * MAXT + i] : 0.0f;
        __syncthreads();

        if (tid < STKD) d_V[((size_t)b * MAXT + t) * STKD + tid] = so[tid];
        float u_ = sigf(so[192]);
        float dd = sigf(so[193]);

        // per-32-chunk inclusive suffix scans
        for (int cch = wid; cch < 9; cch += 8) {
            float v = ss[cch * 32 + lane];
#pragma unroll
            for (int o = 1; o < 32; o <<= 1) {
                float tv = __shfl_down_sync(0xffffffffu, v, o);
                if (lane + o < 32) v += tv;
            }
            ssuf[cch * 32 + lane] = v;
            if (lane == 0) csum[cch] = v;
        }
        __syncthreads();
        if (wid == 0) {
            float tv = (lane < 9) ? csum[lane] : 0.0f;
            float vv = tv;
#pragma unroll
            for (int o = 1; o < 16; o <<= 1) {
                float sh = __shfl_down_sync(0xffffffffu, vv, o);
                if (lane + o < 16) vv += sh;
            }
            if (lane < 9) csum[lane] = vv - tv;   // strict suffix of chunk totals
        }
        __syncthreads();

        for (int i = tid; i < MAXT; i += NTHR) {
            float si   = ss[i];
            float prod = ssuf[i] + csum[i >> 5] - si;     // sum_{j>i} s[j]
            float sp   = fmaxf(0.0f, si - fmaxf(0.0f, u_ - prod));
            if (i == t) sp = dd;
            float inner = fmaxf(0.0f, 1.0f - prod - sp);
            sA[i] = fminf(sp, inner);
            if (i <= t) d_s[b * MAXT + i] = sp;
        }
        __syncthreads();

        // r_t[d] = sum_{i<=t} A[i] * V[b][i][d]  -> stored transposed
        {
            const int dcol = tid & 63, q = tid >> 6;
            float acc = 0.0f;
            for (int i = q; i <= t; i += 4)
                acc += sA[i] * d_V[((size_t)b * MAXT + i) * STKD + dcol];
            sred[q * 64 + dcol] = acc;
        }
        __syncthreads();
        if (tid < STKD)
            d_RH[(size_t)tid * 128 + b] =
                sred[tid] + sred[64 + tid] + sred[128 + tid] + sred[192 + tid];

        if (t >= KSTART) {
            __syncthreads();
            float v = (tid < INPD) ? so[STKD + tid] : -1e30f;
            float m = v;
#pragma unroll
            for (int o = 16; o; o >>= 1) m = fmaxf(m, __shfl_xor_sync(0xffffffffu, m, o));
            if (lane == 0) csum[wid] = m;
            __syncthreads();
            float mm = csum[0];
#pragma unroll
            for (int w = 1; w < 8; ++w) mm = fmaxf(mm, csum[w]);
            float e = (tid < INPD) ? expf(v - mm) : 0.0f;
#pragma unroll
            for (int o = 16; o; o >>= 1) e += __shfl_xor_sync(0xffffffffu, e, o);
            if (lane == 0) csum[8 + wid] = e;
            __syncthreads();
            float tot = 0.0f;
#pragma unroll
            for (int w = 0; w < 8; ++w) tot += csum[8 + w];
            float ls = logf(tot);
            if (tid < INPD)
                out[(((size_t)(t - KSTART)) * BATCH + b) * INPD + tid] = v - mm - ls;
        }
        grid_sync(n);
    }
}

extern "C" void kernel_launch(void *const *d_in, const int *in_sizes, int n_in,
                              void *d_out, int out_size) {
    (void)in_sizes; (void)n_in; (void)out_size;
    const float *x   = (const float *)d_in[0];
    const float *Wih = (const float *)d_in[1];
    const float *bih = (const float *)d_in[2];
    const float *Whh = (const float *)d_in[3];
    const float *bhh = (const float *)d_in[4];
    const float *Wr  = (const float *)d_in[5];
    const float *br  = (const float *)d_in[6];
    float *out = (float *)d_out;

    cudaFuncSetAttribute(lstm_stack_kernel,
                         cudaFuncAttributeMaxDynamicSharedMemorySize, SMEMB);

    void *p;
    cudaGetSymbolAddress(&p, d_RH);  cudaMemsetAsync(p, 0, sizeof(float) * (64 + 1024) * 128);
    cudaGetSymbolAddress(&p, d_s);   cudaMemsetAsync(p, 0, sizeof(float) * BATCH * MAXT);
    cudaGetSymbolAddress(&p, g_bar); cudaMemsetAsync(p, 0, sizeof(unsigned));

    lstm_stack_kernel<<<GRIDN, NTHR, SMEMB>>>(x, Wih, bih, Whh, bhh, Wr, br, out);
}

// round 5
// speedup vs baseline: 1.1039x; 1.1003x over previous
#include <cuda_runtime.h>
#include <math.h>
#include <stdint.h>

// ---------------------------------------------------------------------------
// LSTM + differentiable stack, 259 sequential steps, persistent kernel.
// 128 CTAs, 3 grid barriers per step.
//  Phase A: CTA n -> 16 gate cols (4 units x 4 gates), all 128 batches, full K.
//           Weights resident in SMEM (dup f32x2). A streamed [k][b] in 64-k
//           chunks via cp.async.bulk (TMA) double buffer + mbarriers.
//           FFMA2 inner loop. Epilogue: LSTM cell (c in SMEM), h written both
//           transposed (for next-step TMA) and batch-major (for readout).
//  Phase R: 49 CTAs: o194 = h @ Wr^T + br  (Wr slice cached in SMEM).
//  Phase S: CTA b: stack update (suffix scan, A, r_t -> transposed) +
//           log-softmax out for t >= 129.
// ---------------------------------------------------------------------------

#define BATCH   128
#define HID     512
#define INPD    128
#define STKD    64
#define MAXT    259
#define NSTEPS  259
#define KSTART  129
#define OCOLS   194

#define GRIDN   128
#define NTHR    256
#define KCH     64                       // k rows per chunk
#define CHB     (KCH * BATCH * 4)        // 32768 bytes per chunk

// smem layout (float offsets)
#define OFF_WD  0                        // 11264 u64 (W dup f32x2) = 22528 f
#define OFF_AS  22528                    // 2 x (64 x 128) A chunk buffers
#define OFF_GS  38912                    // 16 x 132 gate exchange
#define OFF_SC  41024                    // 512 c-state
#define OFF_SB  41536                    // 16 bias
#define OFF_MB  41552                    // 2 mbarriers (16 bytes)
#define SMEMF   41560
#define SMEMB   (SMEMF * 4)

__device__ float d_xT[129 * 128 * 128];      // x transposed [t][k][b]
__device__ float d_RH[(64 + 1024) * 128];    // rows: 0..63 r ; 64..575 h0 ; 576..1087 h1
__device__ float d_h[BATCH * HID];           // batch-major h (for readout)
__device__ float d_s[BATCH * MAXT];
__device__ float d_V[BATCH * MAXT * STKD];
__device__ float d_o194[BATCH * OCOLS];
__device__ unsigned g_bar;

__device__ __forceinline__ float sigf(float x) { return 1.0f / (1.0f + expf(-x)); }

#define FFMA2(acc, a, w) \
    asm volatile("fma.rn.f32x2 %0, %1, %2, %0;" : "+l"(acc) : "l"(a), "l"(w))

__device__ __forceinline__ void grid_sync(unsigned &n) {
    __syncthreads();
    n += (unsigned)GRIDN;
    if (threadIdx.x == 0) {
        __threadfence();
        atomicAdd(&g_bar, 1u);
        while (*((volatile unsigned *)&g_bar) < n) { __nanosleep(32); }
        __threadfence();
    }
    __syncthreads();
}

__device__ __forceinline__ void mbar_init(uint32_t mbar) {
    asm volatile("mbarrier.init.shared.b64 [%0], %1;" :: "r"(mbar), "r"(1u) : "memory");
}
__device__ __forceinline__ void mbar_expect(uint32_t mbar, uint32_t bytes) {
    asm volatile("mbarrier.arrive.expect_tx.shared.b64 _, [%0], %1;"
                 :: "r"(mbar), "r"(bytes) : "memory");
}
__device__ __forceinline__ void bulk_ld(uint32_t dst, const float *src,
                                        uint32_t bytes, uint32_t mbar) {
    asm volatile("cp.async.bulk.shared::cluster.global.mbarrier::complete_tx::bytes "
                 "[%0], [%1], %2, [%3];"
                 :: "r"(dst), "l"(src), "r"(bytes), "r"(mbar) : "memory");
}
__device__ __forceinline__ void mbar_wait(uint32_t mbar, uint32_t parity) {
    asm volatile(
        "{\n\t.reg .pred P;\n\t"
        "WL_%=:\n\t"
        "mbarrier.try_wait.parity.acquire.cta.shared::cta.b64 P, [%0], %1, 0x989680;\n\t"
        "@P bra.uni WD_%=;\n\t"
        "bra.uni WL_%=;\n\t"
        "WD_%=:\n\t}"
        :: "r"(mbar), "r"(parity) : "memory");
}

__device__ __forceinline__ const float *chunk_src(int ca, int t, int hrd) {
    if (ca < 2)  return d_xT + ((size_t)t * 128 + ca * 64) * 128;
    if (ca == 2) return d_RH;                                     // r rows
    return d_RH + (size_t)(64 + hrd * 512 + (ca - 3) * 64) * 128; // h rows
}

__global__ void __launch_bounds__(NTHR, 1)
lstm_stack_kernel(const float *__restrict__ x,
                  const float *__restrict__ Wih, const float *__restrict__ bih,
                  const float *__restrict__ Whh, const float *__restrict__ bhh,
                  const float *__restrict__ Wr, const float *__restrict__ br,
                  float *__restrict__ out) {
    extern __shared__ __align__(16) float smf[];
    unsigned long long *Wd = (unsigned long long *)(smf + OFF_WD);
    float *As = smf + OFF_AS;
    float *gs = smf + OFF_GS;
    float *sc = smf + OFF_SC;
    float *sb = smf + OFF_SB;
    // phase R/S scratch aliases the A-buffer region (TMA idle there)
    float *so   = smf + OFF_AS;        // 208
    float *ss   = smf + OFF_AS + 208;  // 288
    float *ssuf = smf + OFF_AS + 496;  // 288
    float *sA   = smf + OFF_AS + 784;  // 288
    float *csum = smf + OFF_AS + 1072; // 16
    float *sred = smf + OFF_AS + 1088; // 256
    float *Wsr  = smf + OFF_AS;        // 2048 (phase R)

    const int tid  = threadIdx.x;
    const int bidx = blockIdx.x;
    const int lane = tid & 31, wid = tid >> 5;
    unsigned n = 0;

    const uint32_t mb0 = (uint32_t)__cvta_generic_to_shared(smf + OFF_MB);
    const uint32_t mb1 = mb0 + 8;
    const uint32_t asb0 = (uint32_t)__cvta_generic_to_shared(As);
    const uint32_t asb1 = asb0 + CHB;
    if (tid == 0) { mbar_init(mb0); mbar_init(mb1); }
    __syncthreads();
    unsigned ph = 0;   // bit0: buf0 phase, bit1: buf1 phase

    // ---------------- prologue: transpose x[t] -> d_xT[t][k][b] -------------
    {
        float *tile = smf;  // 128x132 scratch (overlaps Wd; W loaded later)
        for (int p = bidx; p < KSTART; p += GRIDN) {
#pragma unroll
            for (int q = 0; q < 16; ++q) {
                int idx = q * 1024 + tid * 4;
                int b = idx >> 7, k = idx & 127;
                float4 v = *(const float4 *)(x + ((size_t)p * 128 + b) * 128 + k);
                tile[b * 132 + k]     = v.x;
                tile[b * 132 + k + 1] = v.y;
                tile[b * 132 + k + 2] = v.z;
                tile[b * 132 + k + 3] = v.w;
            }
            __syncthreads();
#pragma unroll
            for (int q = 0; q < 16; ++q) {
                int idx = q * 1024 + tid * 4;
                int k = idx >> 7, b = idx & 127;
                float4 v = make_float4(tile[b * 132 + k], tile[(b + 1) * 132 + k],
                                       tile[(b + 2) * 132 + k], tile[(b + 3) * 132 + k]);
                *(float4 *)(d_xT + ((size_t)p * 128 + k) * 128 + b) = v;
            }
            __syncthreads();
        }
    }
    grid_sync(n);

    // ---------------- persistent: W dup f32x2, bias, c-state ----------------
    for (int idx = tid; idx < 704 * 16; idx += NTHR) {
        int k = idx >> 4, cidx = idx & 15;
        int m = cidx >> 2, u = cidx & 3;
        int grow = m * 512 + bidx * 4 + u;
        float w = (k < 192) ? Wih[(size_t)grow * 192 + k]
                            : Whh[(size_t)grow * 512 + (k - 192)];
        unsigned ub = __float_as_uint(w);
        Wd[idx] = (unsigned long long)ub | ((unsigned long long)ub << 32);
    }
    if (tid < 16) {
        int m = tid >> 2, u = tid & 3;
        int grow = m * 512 + bidx * 4 + u;
        sb[tid] = bih[grow] + bhh[grow];
    }
    for (int idx = tid; idx < 512; idx += NTHR) sc[idx] = 0.0f;
    __syncthreads();

    const int tx = tid & 15;   // gate column within 16
    const int ty = tid >> 4;   // batch octet 0..15

    // =========================== main time loop =============================
    for (int t = 0; t < NSTEPS; ++t) {
        const int hrd = t & 1, hwr = (t + 1) & 1;
        const int cbase = (t < KSTART) ? 0 : 2;
        const int nch   = 11 - cbase;

        // ---------------- Phase A: gate GEMM + cell ----------------
        unsigned long long acc0 = 0ull, acc1 = 0ull, acc2 = 0ull, acc3 = 0ull;
        if (tid == 0) {
            mbar_expect(mb0, CHB);
            bulk_ld(asb0, chunk_src(cbase, t, hrd), CHB, mb0);
        }
        for (int ci = 0; ci < nch; ++ci) {
            const int cb = ci & 1;
            if (ci + 1 < nch && tid == 0) {
                const uint32_t mbn = cb ? mb0 : mb1;
                mbar_expect(mbn, CHB);
                bulk_ld(cb ? asb0 : asb1, chunk_src(cbase + ci + 1, t, hrd), CHB, mbn);
            }
            mbar_wait(cb ? mb1 : mb0, (ph >> cb) & 1u);
            ph ^= (1u << cb);

            const float *Ab = As + cb * (KCH * BATCH);
            const int kg0 = (cbase + ci) * KCH;
#pragma unroll 8
            for (int kk = 0; kk < KCH; ++kk) {
                const ulonglong2 *ap = (const ulonglong2 *)(Ab + kk * 128 + ty * 8);
                ulonglong2 a01 = ap[0];
                ulonglong2 a23 = ap[1];
                unsigned long long w = Wd[(kg0 + kk) * 16 + tx];
                FFMA2(acc0, a01.x, w);
                FFMA2(acc1, a01.y, w);
                FFMA2(acc2, a23.x, w);
                FFMA2(acc3, a23.y, w);
            }
            __syncthreads();
        }
        // epilogue: unpack + bias -> gs[col][b]
        {
            float bsum = sb[tx];
            float v0 = __uint_as_float((unsigned)acc0) + bsum;
            float v1 = __uint_as_float((unsigned)(acc0 >> 32)) + bsum;
            float v2 = __uint_as_float((unsigned)acc1) + bsum;
            float v3 = __uint_as_float((unsigned)(acc1 >> 32)) + bsum;
            float v4 = __uint_as_float((unsigned)acc2) + bsum;
            float v5 = __uint_as_float((unsigned)(acc2 >> 32)) + bsum;
            float v6 = __uint_as_float((unsigned)acc3) + bsum;
            float v7 = __uint_as_float((unsigned)(acc3 >> 32)) + bsum;
            float *gp = gs + tx * 132 + ty * 8;
            *(float4 *)gp       = make_float4(v0, v1, v2, v3);
            *(float4 *)(gp + 4) = make_float4(v4, v5, v6, v7);
        }
        __syncthreads();
        // cell update: this CTA's 4 hidden units, all 128 batches
#pragma unroll
        for (int r = 0; r < 2; ++r) {
            int idx = tid + r * NTHR;        // 0..511
            int u = idx >> 7, b = idx & 127;
            float gi = gs[u * 132 + b];
            float gf = gs[(4 + u) * 132 + b];
            float gg = gs[(8 + u) * 132 + b];
            float go = gs[(12 + u) * 132 + b];
            float ig = sigf(gi), fg = sigf(gf);
            float tg = tanhf(gg), og = sigf(go);
            float c2 = fg * sc[idx] + ig * tg;
            sc[idx] = c2;
            float h2 = og * tanhf(c2);
            d_RH[(size_t)(64 + hwr * 512 + bidx * 4 + u) * 128 + b] = h2;
            d_h[(size_t)b * HID + bidx * 4 + u] = h2;
        }
        grid_sync(n);

        // ---------------- Phase R: readout (49 CTAs) ----------------
        if (bidx < 49) {
            const int n0 = bidx * 4;
            for (int idx = tid; idx < 4 * HID; idx += NTHR) {
                int cc = idx >> 9, k = idx & 511, nn = n0 + cc;
                Wsr[idx] = (nn < OCOLS) ? Wr[(size_t)nn * HID + k] : 0.0f;
            }
            __syncthreads();
            const int b  = tid >> 1;
            const int kh = tid & 1;
            const float4 *hv = (const float4 *)(d_h + (size_t)b * HID + kh * 256);
            float acc[4] = {0.f, 0.f, 0.f, 0.f};
#pragma unroll 8
            for (int k4 = 0; k4 < 64; ++k4) {
                float4 h4 = hv[k4];
                int kk = kh * 256 + k4 * 4;
#pragma unroll
                for (int cc = 0; cc < 4; ++cc) {
                    const float *w = Wsr + cc * HID + kk;
                    acc[cc] += h4.x * w[0] + h4.y * w[1] + h4.z * w[2] + h4.w * w[3];
                }
            }
#pragma unroll
            for (int cc = 0; cc < 4; ++cc)
                acc[cc] += __shfl_down_sync(0xffffffffu, acc[cc], 1);
            if (kh == 0) {
#pragma unroll
                for (int cc = 0; cc < 4; ++cc) {
                    int nn = n0 + cc;
                    if (nn < OCOLS) d_o194[b * OCOLS + nn] = acc[cc] + br[nn];
                }
            }
        }
        grid_sync(n);

        // ---------------- Phase S: stack update (CTA = batch row) ----------
        const int b = bidx;
        if (tid < OCOLS) so[tid] = d_o194[b * OCOLS + tid];
        for (int i = tid; i < 288; i += NTHR)
            ss[i] = (i < MAXT) ? d_s[b * MAXT + i] : 0.0f;
        __syncthreads();

        if (tid < STKD) d_V[((size_t)b * MAXT + t) * STKD + tid] = so[tid];
        float u_ = sigf(so[192]);
        float dd = sigf(so[193]);

        for (int cch = wid; cch < 9; cch += 8) {
            float v = ss[cch * 32 + lane];
#pragma unroll
            for (int o = 1; o < 32; o <<= 1) {
                float tv = __shfl_down_sync(0xffffffffu, v, o);
                if (lane + o < 32) v += tv;
            }
            ssuf[cch * 32 + lane] = v;
            if (lane == 0) csum[cch] = v;
        }
        __syncthreads();
        if (wid == 0) {
            float tv = (lane < 9) ? csum[lane] : 0.0f;
            float vv = tv;
#pragma unroll
            for (int o = 1; o < 16; o <<= 1) {
                float sh = __shfl_down_sync(0xffffffffu, vv, o);
                if (lane + o < 16) vv += sh;
            }
            if (lane < 9) csum[lane] = vv - tv;
        }
        __syncthreads();

        for (int i = tid; i < MAXT; i += NTHR) {
            float si   = ss[i];
            float prod = ssuf[i] + csum[i >> 5] - si;
            float sp   = fmaxf(0.0f, si - fmaxf(0.0f, u_ - prod));
            if (i == t) sp = dd;
            float inner = fmaxf(0.0f, 1.0f - prod - sp);
            sA[i] = fminf(sp, inner);
            if (i <= t) d_s[b * MAXT + i] = sp;
        }
        __syncthreads();

        {
            const int dcol = tid & 63, q = tid >> 6;
            float acc = 0.0f;
            for (int i = q; i <= t; i += 4)
                acc += sA[i] * d_V[((size_t)b * MAXT + i) * STKD + dcol];
            sred[q * 64 + dcol] = acc;
        }
        __syncthreads();
        if (tid < STKD)
            d_RH[(size_t)tid * 128 + b] =
                sred[tid] + sred[64 + tid] + sred[128 + tid] + sred[192 + tid];

        if (t >= KSTART) {
            __syncthreads();
            float v = (tid < INPD) ? so[STKD + tid] : -1e30f;
            float m = v;
#pragma unroll
            for (int o = 16; o; o >>= 1) m = fmaxf(m, __shfl_xor_sync(0xffffffffu, m, o));
            if (lane == 0) csum[wid] = m;
            __syncthreads();
            float mm = csum[0];
#pragma unroll
            for (int w = 1; w < 8; ++w) mm = fmaxf(mm, csum[w]);
            float e = (tid < INPD) ? expf(v - mm) : 0.0f;
#pragma unroll
            for (int o = 16; o; o >>= 1) e += __shfl_xor_sync(0xffffffffu, e, o);
            if (lane == 0) csum[8 + wid] = e;
            __syncthreads();
            float tot = 0.0f;
#pragma unroll
            for (int w = 0; w < 8; ++w) tot += csum[8 + w];
            float ls = logf(tot);
            if (tid < INPD)
                out[(((size_t)(t - KSTART)) * BATCH + b) * INPD + tid] = v - mm - ls;
        }
        grid_sync(n);
    }
}

extern "C" void kernel_launch(void *const *d_in, const int *in_sizes, int n_in,
                              void *d_out, int out_size) {
    (void)in_sizes; (void)n_in; (void)out_size;
    const float *x   = (const float *)d_in[0];
    const float *Wih = (const float *)d_in[1];
    const float *bih = (const float *)d_in[2];
    const float *Whh = (const float *)d_in[3];
    const float *bhh = (const float *)d_in[4];
    const float *Wr  = (const float *)d_in[5];
    const float *br  = (const float *)d_in[6];
    float *out = (float *)d_out;

    cudaFuncSetAttribute(lstm_stack_kernel,
                         cudaFuncAttributeMaxDynamicSharedMemorySize, SMEMB);

    void *p;
    cudaGetSymbolAddress(&p, d_RH);  cudaMemsetAsync(p, 0, sizeof(float) * (64 + 1024) * 128);
    cudaGetSymbolAddress(&p, d_s);   cudaMemsetAsync(p, 0, sizeof(float) * BATCH * MAXT);
    cudaGetSymbolAddress(&p, g_bar); cudaMemsetAsync(p, 0, sizeof(unsigned));

    lstm_stack_kernel<<<GRIDN, NTHR, SMEMB>>>(x, Wih, bih, Whh, bhh, Wr, br, out);
}